// round 2
// baseline (speedup 1.0000x reference)
#include <cuda_runtime.h>

#define CIN   64
#define CO    64
#define K2    9
#define FEAT  1152      // 2 * 576
#define N1    576       // W1 cols
#define N2    4096      // W2 cols
#define HW    128
#define TILE  32        // pixels per block
#define NTHREADS 256
#define FS    1153      // feat smem row stride (odd -> conflict free)
#define PER_TENSOR (4 * CO * HW * HW)   // 4,194,304 elements per output tensor

// dynamic smem: feat[32][1153] + yr/mr/sr[32][64]*3
#define SMEM_FLOATS (TILE * FS + 3 * TILE * 64)
#define SMEM_BYTES  (SMEM_FLOATS * 4)

__global__ __launch_bounds__(NTHREADS, 1)
void fused_kpn_kernel(const float* __restrict__ x,
                      const float* __restrict__ m,
                      const float* __restrict__ s,
                      const float* __restrict__ W1,
                      const float* __restrict__ b1,
                      const float* __restrict__ W2,
                      const float* __restrict__ b2,
                      float* __restrict__ out)
{
    extern __shared__ float sm[];
    float* feat = sm;                       // [32][1153]
    float* yr_s = sm + TILE * FS;           // [32][64]
    float* mr_s = yr_s + TILE * 64;         // [32][64]
    float* sr_s = mr_s + TILE * 64;         // [32][64]

    const int tid  = threadIdx.x;
    const int pix0 = blockIdx.x * TILE;
    const int b    = pix0 >> 14;            // pix0 / 16384
    const int h    = (pix0 >> 7) & 127;
    const int w0   = pix0 & 127;            // 0,32,64,96

    // ---- zero reduction arrays ----
    for (int i = tid; i < TILE * 64 * 3; i += NTHREADS) yr_s[i] = 0.0f;

    // ---- gather feat tile: feat[pix][f], f = (c*9 + kh*3 + kw) (+576 for m) ----
    const float* base_x = x + (size_t)b * (CIN * HW * HW);
    const float* base_m = m + (size_t)b * (CIN * HW * HW);
    for (int idx = tid; idx < TILE * FEAT; idx += NTHREADS) {
        int pix = idx & 31;
        int f   = idx >> 5;
        const float* src = base_x;
        int fr = f;
        if (f >= N1) { src = base_m; fr = f - N1; }
        int c  = fr / 9;
        int k  = fr - c * 9;
        int kh = k / 3;
        int kw = k - kh * 3;
        int hh = h + kh - 1;  hh = max(0, min(HW - 1, hh));
        int ww = w0 + pix + kw - 1;  ww = max(0, min(HW - 1, ww));
        feat[pix * FS + f] = src[(c * HW + hh) * HW + ww];
    }
    __syncthreads();

    const int col = tid & 63;               // output column within tile
    const int pg  = tid >> 6;               // pixel group 0..3 (8 pixels each)
    const float* featp = feat + (pg * 8) * FS;

    // ==================== Phase A: w1 = feat @ W1 + b1, reduce to yr/mr/sr ===
    for (int jt = 0; jt < 9; jt++) {
        const int j = jt * 64 + col;        // j in [0,576)
        float acc[8];
        #pragma unroll
        for (int p = 0; p < 8; p++) acc[p] = 0.0f;

        const float* wp = W1 + j;
        #pragma unroll 4
        for (int f = 0; f < FEAT; f++) {
            float wv = __ldg(wp + f * N1);
            #pragma unroll
            for (int p = 0; p < 8; p++)
                acc[p] = fmaf(featp[p * FS + f], wv, acc[p]);
        }

        const float bj = __ldg(b1 + j);
        const int c  = j / 9;
        const int k  = j - c * 9;
        const int kh = k / 3;
        const int kw = k - kh * 3;
        const int hh = max(0, min(HW - 1, h + kh - 1));
        const float* sp_row = s + (((size_t)b * CIN + c) * HW + hh) * HW;

        #pragma unroll
        for (int p = 0; p < 8; p++) {
            int pix = pg * 8 + p;
            float w1v = acc[p] + bj;
            float aw  = fabsf(w1v);
            int ww = max(0, min(HW - 1, w0 + pix + kw - 1));
            atomicAdd(&yr_s[pix * 64 + c], feat[pix * FS + j] * w1v);
            atomicAdd(&mr_s[pix * 64 + c], feat[pix * FS + N1 + j] * aw);
            atomicAdd(&sr_s[pix * 64 + c], sp_row[ww] * aw);
        }
    }
    __syncthreads();

    // ==================== Phase B: w2 = feat @ W2 + b2, fused channel sum ====
    float ya[8], ma[8], sa[8];
    #pragma unroll
    for (int p = 0; p < 8; p++) { ya[p] = 0.0f; ma[p] = 0.0f; sa[p] = 0.0f; }

    for (int cg = 0; cg < 32; cg++) {
        const int j0 = cg * 128 + col;      // c0 = 2cg, o = col
        float a0[8], a1[8];
        #pragma unroll
        for (int p = 0; p < 8; p++) { a0[p] = 0.0f; a1[p] = 0.0f; }

        const float* wp = W2 + j0;
        #pragma unroll 2
        for (int f = 0; f < FEAT; f++) {
            float wv0 = __ldg(wp + f * N2);
            float wv1 = __ldg(wp + f * N2 + 64);
            #pragma unroll
            for (int p = 0; p < 8; p++) {
                float v = featp[p * FS + f];
                a0[p] = fmaf(v, wv0, a0[p]);
                a1[p] = fmaf(v, wv1, a1[p]);
            }
        }

        const float bb0 = __ldg(b2 + j0);
        const float bb1 = __ldg(b2 + j0 + 64);
        const int c0 = 2 * cg, c1 = c0 + 1;
        #pragma unroll
        for (int p = 0; p < 8; p++) {
            int pix = pg * 8 + p;
            float v0 = a0[p] + bb0;
            float v1 = a1[p] + bb1;
            float av0 = fabsf(v0), av1 = fabsf(v1);
            ya[p] += yr_s[pix * 64 + c0] * v0  + yr_s[pix * 64 + c1] * v1;
            ma[p] += mr_s[pix * 64 + c0] * av0 + mr_s[pix * 64 + c1] * av1;
            sa[p] += sr_s[pix * 64 + c0] * av0 + sr_s[pix * 64 + c1] * av1;
        }
    }
    __syncthreads();

    // ==================== stage outputs in smem, write coalesced =============
    float* sty = feat;                 // [32][65]
    float* stm = feat + TILE * 65;     // [32][65]
    #pragma unroll
    for (int p = 0; p < 8; p++) {
        int pix = pg * 8 + p;
        sty[pix * 65 + col] = ya[p];
        stm[pix * 65 + col] = ma[p] / sa[p];
    }
    __syncthreads();

    for (int t = tid; t < TILE * CO; t += NTHREADS) {
        int o   = t >> 5;
        int pix = t & 31;
        size_t gi = (((size_t)b * CO + o) * HW + h) * HW + w0 + pix;
        out[gi]                  = sty[pix * 65 + o];
        out[gi + PER_TENSOR]     = stm[pix * 65 + o];
        out[gi + 2 * PER_TENSOR] = 1.0f;
    }
}

extern "C" void kernel_launch(void* const* d_in, const int* in_sizes, int n_in,
                              void* d_out, int out_size)
{
    const float* x  = (const float*)d_in[0];
    const float* m  = (const float*)d_in[1];
    const float* s  = (const float*)d_in[2];
    const float* W1 = (const float*)d_in[3];
    const float* b1 = (const float*)d_in[4];
    const float* W2 = (const float*)d_in[5];
    const float* b2 = (const float*)d_in[6];
    float* out = (float*)d_out;

    cudaFuncSetAttribute(fused_kpn_kernel,
                         cudaFuncAttributeMaxDynamicSharedMemorySize, SMEM_BYTES);

    const int nblocks = (4 * HW * HW) / TILE;   // 2048
    fused_kpn_kernel<<<nblocks, NTHREADS, SMEM_BYTES>>>(x, m, s, W1, b1, W2, b2, out);
}

// round 3
// speedup vs baseline: 2.0231x; 2.0231x over previous
#include <cuda_runtime.h>

#define CIN   64
#define CO    64
#define FEAT  1152
#define N1    576
#define N2    4096
#define HW    128
#define TILE  32
#define NTH   512
#define FS2   34                         // padded pixel stride per f (floats, even)
#define PER_TENSOR (4 * CO * HW * HW)

#define SMEM_FLOATS (FEAT * FS2 + 3 * TILE * 64)
#define SMEM_BYTES  (SMEM_FLOATS * 4)    // 181,248 B

typedef unsigned long long ull;

__device__ __forceinline__ ull pack2(float v) {
    ull r; asm("mov.b64 %0, {%1, %1};" : "=l"(r) : "f"(v)); return r;
}
__device__ __forceinline__ void fma2(ull& a, ull x, ull y) {
    asm("fma.rn.f32x2 %0, %1, %2, %0;" : "+l"(a) : "l"(x), "l"(y));
}
__device__ __forceinline__ float2 unpk(ull v) {
    float2 f; asm("mov.b64 {%0, %1}, %2;" : "=f"(f.x), "=f"(f.y) : "l"(v)); return f;
}

__global__ __launch_bounds__(NTH, 1)
void fused_kpn_kernel(const float* __restrict__ x,
                      const float* __restrict__ m,
                      const float* __restrict__ s,
                      const float* __restrict__ W1,
                      const float* __restrict__ b1,
                      const float* __restrict__ W2,
                      const float* __restrict__ b2,
                      float* __restrict__ out)
{
    extern __shared__ float sm[];
    float* featT = sm;                       // [FEAT][FS2], pixel-major rows
    float* yr_s  = sm + FEAT * FS2;          // [32][64]
    float* mr_s  = yr_s + TILE * 64;
    float* sr_s  = mr_s + TILE * 64;

    const int tid  = threadIdx.x;
    const int pix0 = blockIdx.x * TILE;
    const int b    = pix0 >> 14;
    const int h    = (pix0 >> 7) & 127;
    const int w0   = pix0 & 127;

    for (int i = tid; i < TILE * 64 * 3; i += NTH) yr_s[i] = 0.0f;

    // ---- gather feat tile (transposed): featT[f][pix] ----
    const float* base_x = x + (size_t)b * (CIN * HW * HW);
    const float* base_m = m + (size_t)b * (CIN * HW * HW);
    for (int idx = tid; idx < TILE * FEAT; idx += NTH) {
        int pix = idx & 31;
        int f   = idx >> 5;
        const float* src = base_x;
        int fr = f;
        if (f >= N1) { src = base_m; fr = f - N1; }
        int c  = fr / 9;
        int k  = fr - c * 9;
        int kh = k / 3;
        int kw = k - kh * 3;
        int hh = max(0, min(HW - 1, h + kh - 1));
        int ww = max(0, min(HW - 1, w0 + pix + kw - 1));
        featT[f * FS2 + pix] = src[(c * HW + hh) * HW + ww];
    }
    __syncthreads();

    const ull* featT2 = (const ull*)featT;   // [f][FS2/2] pixel pairs

    // ==================== Phase A: w1 = feat @ W1 + b1 -> yr/mr/sr ====
    {
        const int colA = tid & 63;           // j column
        const int pgA  = tid >> 6;           // 0..7, 4 pixels each
        for (int jt = 0; jt < 9; jt++) {
            const int j = jt * 64 + colA;
            ull acc0 = 0ull, acc1 = 0ull;
            const float* wp = W1 + j;
            #pragma unroll 4
            for (int f = 0; f < FEAT; f++) {
                ull wv = pack2(wp[f * N1]);
                ull v0 = featT2[f * (FS2 / 2) + pgA * 2 + 0];
                ull v1 = featT2[f * (FS2 / 2) + pgA * 2 + 1];
                fma2(acc0, v0, wv);
                fma2(acc1, v1, wv);
            }
            const float bj = b1[j];
            const int c  = j / 9;
            const int k  = j - c * 9;
            const int kh = k / 3;
            const int kw = k - kh * 3;
            const int hh = max(0, min(HW - 1, h + kh - 1));
            const float* sp_row = s + (((size_t)b * CIN + c) * HW + hh) * HW;

            float2 a01 = unpk(acc0);
            float2 a23 = unpk(acc1);
            float w1v[4] = { a01.x, a01.y, a23.x, a23.y };
            #pragma unroll
            for (int p = 0; p < 4; p++) {
                int pix = pgA * 4 + p;
                float v  = w1v[p] + bj;
                float aw = fabsf(v);
                int ww = max(0, min(HW - 1, w0 + pix + kw - 1));
                atomicAdd(&yr_s[pix * 64 + c], featT[j * FS2 + pix] * v);
                atomicAdd(&mr_s[pix * 64 + c], featT[(N1 + j) * FS2 + pix] * aw);
                atomicAdd(&sr_s[pix * 64 + c], sp_row[ww] * aw);
            }
        }
    }
    __syncthreads();

    // ==================== Phase B: w2 = feat @ W2 + b2, fused channel sum ====
    const int colB = tid & 127;              // 4 cols: j = cg*512 + colB + i*128
    const int pgB  = tid >> 7;               // 0..3, 8 pixels each
    float ya[8], ma[8], sa[8];
    #pragma unroll
    for (int p = 0; p < 8; p++) { ya[p] = 0.0f; ma[p] = 0.0f; sa[p] = 0.0f; }

    for (int cg = 0; cg < 8; cg++) {
        ull acc[4][4];
        #pragma unroll
        for (int i = 0; i < 4; i++)
            #pragma unroll
            for (int pp = 0; pp < 4; pp++) acc[i][pp] = 0ull;

        const float* wp = W2 + cg * 512 + colB;
        #pragma unroll 2
        for (int f = 0; f < FEAT; f++) {
            const float* wrow = wp + (size_t)f * N2;
            ull wv0 = pack2(wrow[0]);
            ull wv1 = pack2(wrow[128]);
            ull wv2 = pack2(wrow[256]);
            ull wv3 = pack2(wrow[384]);
            ull v[4];
            #pragma unroll
            for (int pp = 0; pp < 4; pp++)
                v[pp] = featT2[f * (FS2 / 2) + pgB * 4 + pp];
            #pragma unroll
            for (int pp = 0; pp < 4; pp++) {
                fma2(acc[0][pp], v[pp], wv0);
                fma2(acc[1][pp], v[pp], wv1);
                fma2(acc[2][pp], v[pp], wv2);
                fma2(acc[3][pp], v[pp], wv3);
            }
        }

        #pragma unroll
        for (int i = 0; i < 4; i++) {
            const int j  = cg * 512 + colB + i * 128;
            const int c  = j >> 6;
            const float bb = b2[j];
            #pragma unroll
            for (int pp = 0; pp < 4; pp++) {
                float2 a = unpk(acc[i][pp]);
                int pixA = pgB * 8 + 2 * pp;
                float yrA = yr_s[pixA * 64 + c],     yrB = yr_s[(pixA + 1) * 64 + c];
                float mrA = mr_s[pixA * 64 + c],     mrB = mr_s[(pixA + 1) * 64 + c];
                float srA = sr_s[pixA * 64 + c],     srB = sr_s[(pixA + 1) * 64 + c];
                float vA = a.x + bb, vB = a.y + bb;
                float aA = fabsf(vA), aB = fabsf(vB);
                ya[2 * pp]     += yrA * vA;  ya[2 * pp + 1] += yrB * vB;
                ma[2 * pp]     += mrA * aA;  ma[2 * pp + 1] += mrB * aB;
                sa[2 * pp]     += srA * aA;  sa[2 * pp + 1] += srB * aB;
            }
        }
    }
    __syncthreads();

    // ==================== stage per-half partials, combine, write ====
    // half 0 (colB<64) holds even-channel partials, half 1 odd; sum then divide.
    {
        const int half = colB >> 6;
        const int o    = colB & 63;
        float* sty = sm + half * 3 * 2080;   // [32][65] each
        float* stm = sty + 2080;
        float* sts = stm + 2080;
        #pragma unroll
        for (int p = 0; p < 8; p++) {
            int pix = pgB * 8 + p;
            sty[pix * 65 + o] = ya[p];
            stm[pix * 65 + o] = ma[p];
            sts[pix * 65 + o] = sa[p];
        }
    }
    __syncthreads();

    for (int t = tid; t < TILE * CO; t += NTH) {
        int o   = t >> 5;
        int pix = t & 31;
        float y  = sm[pix * 65 + o]            + sm[3 * 2080 + pix * 65 + o];
        float mm = (sm[2080 + pix * 65 + o]    + sm[4 * 2080 + pix * 65 + o]) /
                   (sm[2 * 2080 + pix * 65 + o] + sm[5 * 2080 + pix * 65 + o]);
        size_t gi = (((size_t)b * CO + o) * HW + h) * HW + w0 + pix;
        out[gi]                  = y;
        out[gi + PER_TENSOR]     = mm;
        out[gi + 2 * PER_TENSOR] = 1.0f;
    }
}

extern "C" void kernel_launch(void* const* d_in, const int* in_sizes, int n_in,
                              void* d_out, int out_size)
{
    const float* x  = (const float*)d_in[0];
    const float* m  = (const float*)d_in[1];
    const float* s  = (const float*)d_in[2];
    const float* W1 = (const float*)d_in[3];
    const float* b1 = (const float*)d_in[4];
    const float* W2 = (const float*)d_in[5];
    const float* b2 = (const float*)d_in[6];
    float* out = (float*)d_out;

    cudaFuncSetAttribute(fused_kpn_kernel,
                         cudaFuncAttributeMaxDynamicSharedMemorySize, SMEM_BYTES);

    const int nblocks = (4 * HW * HW) / TILE;   // 2048
    fused_kpn_kernel<<<nblocks, NTH, SMEM_BYTES>>>(x, m, s, W1, b1, W2, b2, out);
}

// round 4
// speedup vs baseline: 3.1891x; 1.5763x over previous
#include <cuda_runtime.h>

#define CIN   64
#define CO    64
#define FEAT  1152
#define N1    576
#define N2    4096
#define HW    128
#define TILE  32
#define NTH   512
#define FSP   36                         // floats per f-row (144B, 16B aligned)
#define PER_TENSOR (4 * CO * HW * HW)

#define SMEM_FLOATS (FEAT * FSP + 3 * TILE * 64)
#define SMEM_BYTES  (SMEM_FLOATS * 4)    // 190,464 B

typedef unsigned long long ull;

__device__ __forceinline__ ull pack2(float v) {
    ull r; asm("mov.b64 %0, {%1, %1};" : "=l"(r) : "f"(v)); return r;
}
__device__ __forceinline__ void fma2(ull& a, ull x, ull y) {
    asm("fma.rn.f32x2 %0, %1, %2, %0;" : "+l"(a) : "l"(x), "l"(y));
}
__device__ __forceinline__ float2 unpk(ull v) {
    float2 f; asm("mov.b64 {%0, %1}, %2;" : "=f"(f.x), "=f"(f.y) : "l"(v)); return f;
}

__global__ __launch_bounds__(NTH, 1)
void fused_kpn_kernel(const float* __restrict__ x,
                      const float* __restrict__ m,
                      const float* __restrict__ s,
                      const float* __restrict__ W1,
                      const float* __restrict__ b1,
                      const float* __restrict__ W2,
                      const float* __restrict__ b2,
                      float* __restrict__ out)
{
    extern __shared__ float smf[];
    float* featT = smf;                       // [FEAT][FSP]
    float* yr_s  = smf + FEAT * FSP;          // [32][64]
    float* mr_s  = yr_s + TILE * 64;
    float* sr_s  = mr_s + TILE * 64;

    const int tid  = threadIdx.x;
    const int pix0 = blockIdx.x * TILE;
    const int b    = pix0 >> 14;
    const int h    = (pix0 >> 7) & 127;
    const int w0   = pix0 & 127;

    // ---- gather feat tile (transposed): featT[f][pix] ----
    const float* base_x = x + (size_t)b * (CIN * HW * HW);
    const float* base_m = m + (size_t)b * (CIN * HW * HW);
    for (int idx = tid; idx < TILE * FEAT; idx += NTH) {
        int pix = idx & 31;
        int f   = idx >> 5;
        const float* src = base_x;
        int fr = f;
        if (f >= N1) { src = base_m; fr = f - N1; }
        int c  = fr / 9;
        int k  = fr - c * 9;
        int kh = k / 3;
        int kw = k - kh * 3;
        int hh = max(0, min(HW - 1, h + kh - 1));
        int ww = max(0, min(HW - 1, w0 + pix + kw - 1));
        featT[f * FSP + pix] = src[(c * HW + hh) * HW + ww];
    }
    __syncthreads();

    const ull* featT2 = (const ull*)featT;    // [f][18] pixel pairs

    // ============ Phase A: thread owns channel cA (all 9 taps), 4 pixels ====
    {
        const int cA  = tid & 63;
        const int pgA = tid >> 6;             // 0..7, pixels pgA*4..+3
        ull acc[9][2];
        #pragma unroll
        for (int k = 0; k < 9; k++) { acc[k][0] = 0ull; acc[k][1] = 0ull; }

        const float* w1p = W1 + cA * 9;
        #pragma unroll 2
        for (int f = 0; f < FEAT; f++) {
            ull wv[9];
            #pragma unroll
            for (int k = 0; k < 9; k++)
                wv[k] = pack2(__ldg(w1p + (size_t)f * N1 + k));
            ulonglong2 vv = *(const ulonglong2*)(featT2 + f * 18 + pgA * 2);
            #pragma unroll
            for (int k = 0; k < 9; k++) {
                fma2(acc[k][0], vv.x, wv[k]);
                fma2(acc[k][1], vv.y, wv[k]);
            }
        }

        float yrv[4] = {0,0,0,0}, mrv[4] = {0,0,0,0}, srv[4] = {0,0,0,0};
        #pragma unroll
        for (int k = 0; k < 9; k++) {
            const int j  = cA * 9 + k;
            const float bj = b1[j];
            const int kh = k / 3;
            const int kw = k - kh * 3;
            const int hh = max(0, min(HW - 1, h + kh - 1));
            const float* sp_row = s + (((size_t)b * CIN + cA) * HW + hh) * HW;
            float2 a01 = unpk(acc[k][0]);
            float2 a23 = unpk(acc[k][1]);
            float av[4] = { a01.x, a01.y, a23.x, a23.y };
            #pragma unroll
            for (int p = 0; p < 4; p++) {
                int pix = pgA * 4 + p;
                float v  = av[p] + bj;
                float aw = fabsf(v);
                int ww = max(0, min(HW - 1, w0 + pix + kw - 1));
                yrv[p] += featT[j * FSP + pix] * v;
                mrv[p] += featT[(N1 + j) * FSP + pix] * aw;
                srv[p] += sp_row[ww] * aw;
            }
        }
        #pragma unroll
        for (int p = 0; p < 4; p++) {
            int pix = pgA * 4 + p;
            yr_s[pix * 64 + cA] = yrv[p];
            mr_s[pix * 64 + cA] = mrv[p];
            sr_s[pix * 64 + cA] = srv[p];
        }
    }
    __syncthreads();

    // ============ Phase B: w2 = feat @ W2 + b2, fused channel sum ===========
    const int colB = tid & 127;
    const int pgB  = tid >> 7;                // 0..3, 8 pixels each
    float ya[8], ma[8], sa[8];
    #pragma unroll
    for (int p = 0; p < 8; p++) { ya[p] = 0.0f; ma[p] = 0.0f; sa[p] = 0.0f; }

    for (int cg = 0; cg < 8; cg++) {
        ull acc[4][4];
        #pragma unroll
        for (int i = 0; i < 4; i++)
            #pragma unroll
            for (int pp = 0; pp < 4; pp++) acc[i][pp] = 0ull;

        const float* wp = W2 + cg * 512 + colB;
        #pragma unroll 4
        for (int f = 0; f < FEAT; f++) {
            const float* wrow = wp + (size_t)f * N2;
            ull wv0 = pack2(__ldg(wrow));
            ull wv1 = pack2(__ldg(wrow + 128));
            ull wv2 = pack2(__ldg(wrow + 256));
            ull wv3 = pack2(__ldg(wrow + 384));
            const ulonglong2* fp = (const ulonglong2*)(featT2 + f * 18 + pgB * 4);
            ulonglong2 va = fp[0];
            ulonglong2 vb = fp[1];
            ull v[4] = { va.x, va.y, vb.x, vb.y };
            #pragma unroll
            for (int pp = 0; pp < 4; pp++) {
                fma2(acc[0][pp], v[pp], wv0);
                fma2(acc[1][pp], v[pp], wv1);
                fma2(acc[2][pp], v[pp], wv2);
                fma2(acc[3][pp], v[pp], wv3);
            }
        }

        #pragma unroll
        for (int i = 0; i < 4; i++) {
            const int j = cg * 512 + colB + i * 128;
            const int c = j >> 6;
            const float bb = b2[j];
            #pragma unroll
            for (int pp = 0; pp < 4; pp++) {
                float2 a = unpk(acc[i][pp]);
                int pixA = pgB * 8 + 2 * pp;
                float yrA = yr_s[pixA * 64 + c], yrB = yr_s[(pixA + 1) * 64 + c];
                float mrA = mr_s[pixA * 64 + c], mrB = mr_s[(pixA + 1) * 64 + c];
                float srA = sr_s[pixA * 64 + c], srB = sr_s[(pixA + 1) * 64 + c];
                float vA = a.x + bb, vB = a.y + bb;
                float aA = fabsf(vA), aB = fabsf(vB);
                ya[2 * pp]     += yrA * vA;  ya[2 * pp + 1] += yrB * vB;
                ma[2 * pp]     += mrA * aA;  ma[2 * pp + 1] += mrB * aB;
                sa[2 * pp]     += srA * aA;  sa[2 * pp + 1] += srB * aB;
            }
        }
    }
    __syncthreads();

    // ============ stage per-half partials, combine, write ===================
    {
        const int half = colB >> 6;
        const int o    = colB & 63;
        float* sty = smf + half * 3 * 2080;   // [32][65] each
        float* stm = sty + 2080;
        float* sts = stm + 2080;
        #pragma unroll
        for (int p = 0; p < 8; p++) {
            int pix = pgB * 8 + p;
            sty[pix * 65 + o] = ya[p];
            stm[pix * 65 + o] = ma[p];
            sts[pix * 65 + o] = sa[p];
        }
    }
    __syncthreads();

    for (int t = tid; t < TILE * CO; t += NTH) {
        int o   = t >> 5;
        int pix = t & 31;
        float y  = smf[pix * 65 + o]             + smf[3 * 2080 + pix * 65 + o];
        float mm = (smf[2080 + pix * 65 + o]     + smf[4 * 2080 + pix * 65 + o]) /
                   (smf[2 * 2080 + pix * 65 + o] + smf[5 * 2080 + pix * 65 + o]);
        size_t gi = (((size_t)b * CO + o) * HW + h) * HW + w0 + pix;
        out[gi]                  = y;
        out[gi + PER_TENSOR]     = mm;
        out[gi + 2 * PER_TENSOR] = 1.0f;
    }
}

extern "C" void kernel_launch(void* const* d_in, const int* in_sizes, int n_in,
                              void* d_out, int out_size)
{
    const float* x  = (const float*)d_in[0];
    const float* m  = (const float*)d_in[1];
    const float* s  = (const float*)d_in[2];
    const float* W1 = (const float*)d_in[3];
    const float* b1 = (const float*)d_in[4];
    const float* W2 = (const float*)d_in[5];
    const float* b2 = (const float*)d_in[6];
    float* out = (float*)d_out;

    cudaFuncSetAttribute(fused_kpn_kernel,
                         cudaFuncAttributeMaxDynamicSharedMemorySize, SMEM_BYTES);

    const int nblocks = (4 * HW * HW) / TILE;   // 2048
    fused_kpn_kernel<<<nblocks, NTH, SMEM_BYTES>>>(x, m, s, W1, b1, W2, b2, out);
}